// round 7
// baseline (speedup 1.0000x reference)
#include <cuda_runtime.h>
#include <cstdint>

#define NROWS 384
#define DDIM  768
#define KOFF  (NROWS * DDIM)   // element offset between split-k partial buffers

// Split-k partial outputs: g_A[z], g_B[z] for k-half z. Pair kernel sums them.
__device__ float g_A[2][NROWS * DDIM];
__device__ float g_B[2][NROWS * DDIM];

// ---------------------------------------------------------------------------
// Phase 1: split-k GEMM. C = P @ W1half^T. Grid (24, 6, 2): z = k-half.
// BM=BN=64, BK=16, 256 threads, 4x4 per thread, register-prefetch pipeline.
// 288 CTAs -> 2 CTAs/SM. b1 folded into the z=0 partial of g_A. ~27us.
// ---------------------------------------------------------------------------
__global__ void __launch_bounds__(256)
gemm_kernel(const float* __restrict__ P,
            const float* __restrict__ W1,
            const float* __restrict__ b1) {
    __shared__ float Ps[16][68];   // [k][i]
    __shared__ float Qs[16][68];   // [k][j]

    const int t  = threadIdx.x;        // 0..255
    const int tx = t & 15;
    const int ty = t >> 4;
    const int col0 = blockIdx.x * 64;
    const int row0 = blockIdx.y * 64;
    const int z    = blockIdx.z;       // k-half
    const int koff = z * 384;
    const bool isB = (col0 >= DDIM);
    const float* Wbase = W1 + (isB ? (size_t)(col0 - DDIM) * (2 * DDIM) + DDIM
                                   : (size_t)col0 * (2 * DDIM));

    const int lr  = t >> 2;            // 0..63
    const int lc4 = (t & 3) << 2;      // 0,4,8,12

    const float* Psrc = P + (size_t)(row0 + lr) * DDIM + koff + lc4;
    const float* Wsrc = Wbase + (size_t)lr * (2 * DDIM) + koff + lc4;

    float acc[4][4];
#pragma unroll
    for (int a = 0; a < 4; a++)
#pragma unroll
        for (int b = 0; b < 4; b++) acc[a][b] = 0.0f;

    // Prologue: prefetch chunk 0.
    float4 pv = *(const float4*)Psrc;
    float4 wv = *(const float4*)Wsrc;

    for (int k0 = 0; k0 < 384; k0 += 16) {
        Ps[lc4 + 0][lr] = pv.x; Ps[lc4 + 1][lr] = pv.y;
        Ps[lc4 + 2][lr] = pv.z; Ps[lc4 + 3][lr] = pv.w;
        Qs[lc4 + 0][lr] = wv.x; Qs[lc4 + 1][lr] = wv.y;
        Qs[lc4 + 2][lr] = wv.z; Qs[lc4 + 3][lr] = wv.w;
        __syncthreads();

        if (k0 + 16 < 384) {
            pv = *(const float4*)(Psrc + k0 + 16);
            wv = *(const float4*)(Wsrc + k0 + 16);
        }

#pragma unroll
        for (int k = 0; k < 16; k++) {
            float4 av = *(const float4*)&Ps[k][ty << 2];
            float4 bv = *(const float4*)&Qs[k][tx << 2];
            float aa[4] = {av.x, av.y, av.z, av.w};
            float bb[4] = {bv.x, bv.y, bv.z, bv.w};
#pragma unroll
            for (int a = 0; a < 4; a++)
#pragma unroll
                for (int b = 0; b < 4; b++)
                    acc[a][b] = fmaf(aa[a], bb[b], acc[a][b]);
        }
        __syncthreads();
    }

    const int cbase = isB ? (col0 - DDIM) : col0;
    float* dst = (isB ? g_B[z] : g_A[z]);
    const int jc = cbase + (tx << 2);
    float4 badd = make_float4(0.f, 0.f, 0.f, 0.f);
    if (!isB && z == 0) badd = *(const float4*)(b1 + jc);
#pragma unroll
    for (int a = 0; a < 4; a++) {
        const int i = row0 + (ty << 2) + a;
        float4 v = make_float4(acc[a][0] + badd.x, acc[a][1] + badd.y,
                               acc[a][2] + badd.z, acc[a][3] + badd.w);
        *(float4*)(dst + (size_t)i * DDIM + jc) = v;
    }
}

// ---------------------------------------------------------------------------
// Phase 2: fused  out[i,j,c] = sum_d tanh(A[i,d] + B[j,d]) * W2[c,d] + b2[c]
// CTA tile 16i x 32j, 512 threads, d split into 4 quarters (tz, 128 thr each),
// per-thread 2i x 2j micro-tile, chunks of 32 d, stride-34 conflict-free rows.
// KEY CHANGE: __launch_bounds__(512, 3) caps regs ~42 -> 3 CTAs/SM ->
// 12 warps/SMSP (was 8). The verified binder is eligible-warp starvation
// (MUFU at 72% with issue 48%); +50% warps should close most of the gap.
// Inner unroll cut to 4 to shrink live-register footprint.
// ---------------------------------------------------------------------------
#define SPQ 34
#define DQ  192

__global__ void __launch_bounds__(512, 3)
pair_kernel(const float* __restrict__ W2,
            const float* __restrict__ b2,
            float* __restrict__ out) {
    __shared__ float As[4][16 * SPQ];   // 8.7 KB
    __shared__ float Bs[4][32 * SPQ];   // 17.4 KB
    __shared__ float W0a[DDIM];         // 3 KB
    __shared__ float W1a[DDIM];         // 3 KB
    __shared__ float Red[3 * 128 * 8];  // 12 KB   (total ~44 KB; 3 CTAs fit)

    const int t  = threadIdx.x;    // 0..511
    const int tz = t >> 7;         // d-quarter 0..3
    const int tt = t & 127;
    const int tx = tt & 15;        // j-group
    const int ty = tt >> 4;        // i-group 0..7
    const int i0 = blockIdx.y * 16;
    const int j0 = blockIdx.x * 32;

    // One-time W2 strip preload: 1536 floats = 384 float4.
    if (t < 192) {
        *(float4*)&W0a[t << 2] = *(const float4*)(W2 + (t << 2));
    } else if (t < 384) {
        const int c4 = (t - 192) << 2;
        *(float4*)&W1a[c4] = *(const float4*)(W2 + DDIM + c4);
    }

    // Per-chunk load mapping (within quarter): A 16x32 = 128 f4 (1/thread),
    // B 32x32 = 256 f4 (2/thread).
    const int lrow = tt >> 3;           // 0..15
    const int lc4  = (tt & 7) << 2;     // 0..28
    const float* Aptr  = g_A[0] + (size_t)(i0 + lrow) * DDIM + tz * DQ + lc4;
    const float* Bptr0 = g_B[0] + (size_t)(j0 + lrow) * DDIM + tz * DQ + lc4;
    const float* Bptr1 = g_B[0] + (size_t)(j0 + 16 + lrow) * DDIM + tz * DQ + lc4;

    float* Ash = As[tz];
    float* Bsh = Bs[tz];

    float acc0[2][2] = {{0.f, 0.f}, {0.f, 0.f}};   // [ii][jj] class 0
    float acc1[2][2] = {{0.f, 0.f}, {0.f, 0.f}};   // [ii][jj] class 1

    // Prologue: prefetch chunk 0, folding the two split-k partials.
    float4 av, bv0, bv1;
    {
        float4 x = *(const float4*)Aptr,          y = *(const float4*)(Aptr + KOFF);
        av  = make_float4(x.x + y.x, x.y + y.y, x.z + y.z, x.w + y.w);
        x = *(const float4*)Bptr0;  y = *(const float4*)(Bptr0 + KOFF);
        bv0 = make_float4(x.x + y.x, x.y + y.y, x.z + y.z, x.w + y.w);
        x = *(const float4*)Bptr1;  y = *(const float4*)(Bptr1 + KOFF);
        bv1 = make_float4(x.x + y.x, x.y + y.y, x.z + y.z, x.w + y.w);
    }

    for (int c = 0; c < DQ / 32; c++) {
        // Store current chunk (rows 8B-aligned -> float2 stores).
        *(float2*)&Ash[lrow * SPQ + lc4]            = make_float2(av.x, av.y);
        *(float2*)&Ash[lrow * SPQ + lc4 + 2]        = make_float2(av.z, av.w);
        *(float2*)&Bsh[lrow * SPQ + lc4]            = make_float2(bv0.x, bv0.y);
        *(float2*)&Bsh[lrow * SPQ + lc4 + 2]        = make_float2(bv0.z, bv0.w);
        *(float2*)&Bsh[(16 + lrow) * SPQ + lc4]     = make_float2(bv1.x, bv1.y);
        *(float2*)&Bsh[(16 + lrow) * SPQ + lc4 + 2] = make_float2(bv1.z, bv1.w);
        __syncthreads();

        // Prefetch next chunk (hidden under compute).
        if (c + 1 < DQ / 32) {
            const int off = (c + 1) * 32;
            float4 x = *(const float4*)(Aptr + off), y = *(const float4*)(Aptr + off + KOFF);
            av  = make_float4(x.x + y.x, x.y + y.y, x.z + y.z, x.w + y.w);
            x = *(const float4*)(Bptr0 + off);  y = *(const float4*)(Bptr0 + off + KOFF);
            bv0 = make_float4(x.x + y.x, x.y + y.y, x.z + y.z, x.w + y.w);
            x = *(const float4*)(Bptr1 + off);  y = *(const float4*)(Bptr1 + off + KOFF);
            bv1 = make_float4(x.x + y.x, x.y + y.y, x.z + y.z, x.w + y.w);
        }

        const float* Arow0 = &Ash[(2 * ty) * SPQ];
        const float* Arow1 = &Ash[(2 * ty + 1) * SPQ];
        const float* Brow0 = &Bsh[tx * SPQ];
        const float* Brow1 = &Bsh[(tx + 16) * SPQ];
        const float* W0h   = &W0a[tz * DQ + c * 32];
        const float* W1h   = &W1a[tz * DQ + c * 32];

#pragma unroll 4
        for (int dk = 0; dk < 32; dk += 2) {
            const float2 a0  = *(const float2*)&Arow0[dk];
            const float2 a1  = *(const float2*)&Arow1[dk];
            const float2 b0  = *(const float2*)&Brow0[dk];
            const float2 b1v = *(const float2*)&Brow1[dk];
            const float2 w0  = *(const float2*)&W0h[dk];
            const float2 w1  = *(const float2*)&W1h[dk];

            float th;
            // ii=0, jj=0
            asm("tanh.approx.f32 %0, %1;" : "=f"(th) : "f"(a0.x + b0.x));
            acc0[0][0] = fmaf(th, w0.x, acc0[0][0]);
            acc1[0][0] = fmaf(th, w1.x, acc1[0][0]);
            asm("tanh.approx.f32 %0, %1;" : "=f"(th) : "f"(a0.y + b0.y));
            acc0[0][0] = fmaf(th, w0.y, acc0[0][0]);
            acc1[0][0] = fmaf(th, w1.y, acc1[0][0]);
            // ii=0, jj=1
            asm("tanh.approx.f32 %0, %1;" : "=f"(th) : "f"(a0.x + b1v.x));
            acc0[0][1] = fmaf(th, w0.x, acc0[0][1]);
            acc1[0][1] = fmaf(th, w1.x, acc1[0][1]);
            asm("tanh.approx.f32 %0, %1;" : "=f"(th) : "f"(a0.y + b1v.y));
            acc0[0][1] = fmaf(th, w0.y, acc0[0][1]);
            acc1[0][1] = fmaf(th, w1.y, acc1[0][1]);
            // ii=1, jj=0
            asm("tanh.approx.f32 %0, %1;" : "=f"(th) : "f"(a1.x + b0.x));
            acc0[1][0] = fmaf(th, w0.x, acc0[1][0]);
            acc1[1][0] = fmaf(th, w1.x, acc1[1][0]);
            asm("tanh.approx.f32 %0, %1;" : "=f"(th) : "f"(a1.y + b0.y));
            acc0[1][0] = fmaf(th, w0.y, acc0[1][0]);
            acc1[1][0] = fmaf(th, w1.y, acc1[1][0]);
            // ii=1, jj=1
            asm("tanh.approx.f32 %0, %1;" : "=f"(th) : "f"(a1.x + b1v.x));
            acc0[1][1] = fmaf(th, w0.x, acc0[1][1]);
            acc1[1][1] = fmaf(th, w1.x, acc1[1][1]);
            asm("tanh.approx.f32 %0, %1;" : "=f"(th) : "f"(a1.y + b1v.y));
            acc0[1][1] = fmaf(th, w0.y, acc0[1][1]);
            acc1[1][1] = fmaf(th, w1.y, acc1[1][1]);
        }
        __syncthreads();
    }

    // Cross-quarter reduction: quarters 1..3 park 8 partials each, quarter 0 sums.
    if (tz > 0) {
        float* r = &Red[((tz - 1) * 128 + tt) * 8];
        *(float4*)r       = make_float4(acc0[0][0], acc0[0][1], acc0[1][0], acc0[1][1]);
        *(float4*)(r + 4) = make_float4(acc1[0][0], acc1[0][1], acc1[1][0], acc1[1][1]);
    }
    __syncthreads();
    if (tz == 0) {
#pragma unroll
        for (int q = 0; q < 3; q++) {
            const float* r = &Red[(q * 128 + tt) * 8];
            float4 p0 = *(const float4*)r;
            float4 p1 = *(const float4*)(r + 4);
            acc0[0][0] += p0.x; acc0[0][1] += p0.y; acc0[1][0] += p0.z; acc0[1][1] += p0.w;
            acc1[0][0] += p1.x; acc1[0][1] += p1.y; acc1[1][0] += p1.z; acc1[1][1] += p1.w;
        }
        const float bb0 = b2[0];
        const float bb1 = b2[1];
#pragma unroll
        for (int ii = 0; ii < 2; ii++) {
            const int i = i0 + 2 * ty + ii;
#pragma unroll
            for (int jj = 0; jj < 2; jj++) {
                const int j = j0 + tx + 16 * jj;
                float2 o = make_float2(acc0[ii][jj] + bb0, acc1[ii][jj] + bb1);
                *(float2*)(out + ((size_t)i * NROWS + j) * 2) = o;
            }
        }
    }
}

// ---------------------------------------------------------------------------
extern "C" void kernel_launch(void* const* d_in, const int* in_sizes, int n_in,
                              void* d_out, int out_size) {
    const float* P  = (const float*)d_in[0];   // [384, 768]
    const float* W1 = (const float*)d_in[1];   // [768, 1536]
    const float* b1 = (const float*)d_in[2];   // [768]
    const float* W2 = (const float*)d_in[3];   // [2, 768]
    const float* b2 = (const float*)d_in[4];   // [2]
    float* out = (float*)d_out;                // [384, 384, 2]

    gemm_kernel<<<dim3(24, 6, 2), 256>>>(P, W1, b1);
    pair_kernel<<<dim3(12, 24), 512>>>(W2, b2, out);
}

// round 8
// speedup vs baseline: 1.7127x; 1.7127x over previous
#include <cuda_runtime.h>
#include <cstdint>

#define NROWS 384
#define DDIM  768
#define NELEM (NROWS * DDIM)   // 294912 floats per buffer

// Split-k partial outputs. fold_kernel sums [1] into [0]; pair reads [0].
__device__ float g_A[2][NELEM];
__device__ float g_B[2][NELEM];

// ---------------------------------------------------------------------------
// Phase 1: split-k GEMM (round-6 verbatim, measured 27.4us).
// Grid (24, 6, 2): z = k-half. BM=BN=64, BK=16, 256 threads, 4x4/thread,
// register-prefetch pipeline. b1 folded into the z=0 partial of g_A.
// ---------------------------------------------------------------------------
__global__ void __launch_bounds__(256)
gemm_kernel(const float* __restrict__ P,
            const float* __restrict__ W1,
            const float* __restrict__ b1) {
    __shared__ float Ps[16][68];   // [k][i]
    __shared__ float Qs[16][68];   // [k][j]

    const int t  = threadIdx.x;        // 0..255
    const int tx = t & 15;
    const int ty = t >> 4;
    const int col0 = blockIdx.x * 64;
    const int row0 = blockIdx.y * 64;
    const int z    = blockIdx.z;       // k-half
    const int koff = z * 384;
    const bool isB = (col0 >= DDIM);
    const float* Wbase = W1 + (isB ? (size_t)(col0 - DDIM) * (2 * DDIM) + DDIM
                                   : (size_t)col0 * (2 * DDIM));

    const int lr  = t >> 2;            // 0..63
    const int lc4 = (t & 3) << 2;      // 0,4,8,12

    const float* Psrc = P + (size_t)(row0 + lr) * DDIM + koff + lc4;
    const float* Wsrc = Wbase + (size_t)lr * (2 * DDIM) + koff + lc4;

    float acc[4][4];
#pragma unroll
    for (int a = 0; a < 4; a++)
#pragma unroll
        for (int b = 0; b < 4; b++) acc[a][b] = 0.0f;

    float4 pv = *(const float4*)Psrc;
    float4 wv = *(const float4*)Wsrc;

    for (int k0 = 0; k0 < 384; k0 += 16) {
        Ps[lc4 + 0][lr] = pv.x; Ps[lc4 + 1][lr] = pv.y;
        Ps[lc4 + 2][lr] = pv.z; Ps[lc4 + 3][lr] = pv.w;
        Qs[lc4 + 0][lr] = wv.x; Qs[lc4 + 1][lr] = wv.y;
        Qs[lc4 + 2][lr] = wv.z; Qs[lc4 + 3][lr] = wv.w;
        __syncthreads();

        if (k0 + 16 < 384) {
            pv = *(const float4*)(Psrc + k0 + 16);
            wv = *(const float4*)(Wsrc + k0 + 16);
        }

#pragma unroll
        for (int k = 0; k < 16; k++) {
            float4 av = *(const float4*)&Ps[k][ty << 2];
            float4 bv = *(const float4*)&Qs[k][tx << 2];
            float aa[4] = {av.x, av.y, av.z, av.w};
            float bb[4] = {bv.x, bv.y, bv.z, bv.w};
#pragma unroll
            for (int a = 0; a < 4; a++)
#pragma unroll
                for (int b = 0; b < 4; b++)
                    acc[a][b] = fmaf(aa[a], bb[b], acc[a][b]);
        }
        __syncthreads();
    }

    const int cbase = isB ? (col0 - DDIM) : col0;
    float* dst = (isB ? g_B[z] : g_A[z]);
    const int jc = cbase + (tx << 2);
    float4 badd = make_float4(0.f, 0.f, 0.f, 0.f);
    if (!isB && z == 0) badd = *(const float4*)(b1 + jc);
#pragma unroll
    for (int a = 0; a < 4; a++) {
        const int i = row0 + (ty << 2) + a;
        float4 v = make_float4(acc[a][0] + badd.x, acc[a][1] + badd.y,
                               acc[a][2] + badd.z, acc[a][3] + badd.w);
        *(float4*)(dst + (size_t)i * DDIM + jc) = v;
    }
}

// ---------------------------------------------------------------------------
// Phase 1.5: fold split-k partials: g_A[0] += g_A[1]; g_B[0] += g_B[1].
// 73728 float4 per buffer; grid 144 x 256 threads, 2 f4 per thread per buffer.
// Safe under graph replay: gemm re-writes g_*[0] fresh before each fold.
// ---------------------------------------------------------------------------
__global__ void __launch_bounds__(256)
fold_kernel() {
    const int idx = blockIdx.x * 256 + threadIdx.x;   // 0..36863
#pragma unroll
    for (int r = 0; r < 2; r++) {
        const int k = (idx + r * 36864) * 4;          // float offset
        float4 a0 = *(const float4*)&g_A[0][k];
        float4 a1 = *(const float4*)&g_A[1][k];
        *(float4*)&g_A[0][k] = make_float4(a0.x + a1.x, a0.y + a1.y,
                                           a0.z + a1.z, a0.w + a1.w);
        float4 b0 = *(const float4*)&g_B[0][k];
        float4 b1v = *(const float4*)&g_B[1][k];
        *(float4*)&g_B[0][k] = make_float4(b0.x + b1v.x, b0.y + b1v.y,
                                           b0.z + b1v.z, b0.w + b1v.w);
    }
}

// ---------------------------------------------------------------------------
// Phase 2: fused  out[i,j,c] = sum_d tanh(A[i,d] + B[j,d]) * W2[c,d] + b2[c]
// Round-6 structure (16i x 32j, 512 thr, 4 d-quarters, 2i x 2j micro-tile,
// chunk 32, stride-34 conflict-free rows) with SINGLE-SOURCE prefetch:
// no FADD folds in the LDG shadow -> prefetched regs are first consumed at
// the next chunk's STS, 16 iterations later -> LDG latency fully hidden
// (this was the round-5 vs round-6 issue% delta: 54.6 vs 47.7).
// ---------------------------------------------------------------------------
#define SPQ 34
#define DQ  192

__global__ void __launch_bounds__(512, 2)
pair_kernel(const float* __restrict__ W2,
            const float* __restrict__ b2,
            float* __restrict__ out) {
    __shared__ float As[4][16 * SPQ];   // 8.7 KB
    __shared__ float Bs[4][32 * SPQ];   // 17.4 KB
    __shared__ float W0a[DDIM];         // 3 KB
    __shared__ float W1a[DDIM];         // 3 KB
    __shared__ float Red[3 * 128 * 8];  // 12 KB

    const int t  = threadIdx.x;    // 0..511
    const int tz = t >> 7;         // d-quarter 0..3
    const int tt = t & 127;
    const int tx = tt & 15;        // j-group
    const int ty = tt >> 4;        // i-group 0..7
    const int i0 = blockIdx.y * 16;
    const int j0 = blockIdx.x * 32;

    // One-time W2 strip preload: 1536 floats = 384 float4.
    if (t < 192) {
        *(float4*)&W0a[t << 2] = *(const float4*)(W2 + (t << 2));
    } else if (t < 384) {
        const int c4 = (t - 192) << 2;
        *(float4*)&W1a[c4] = *(const float4*)(W2 + DDIM + c4);
    }

    // Per-chunk load mapping (within quarter): A 16x32 = 128 f4 (1/thread),
    // B 32x32 = 256 f4 (2/thread).
    const int lrow = tt >> 3;           // 0..15
    const int lc4  = (tt & 7) << 2;     // 0..28
    const float* Aptr  = g_A[0] + (size_t)(i0 + lrow) * DDIM + tz * DQ + lc4;
    const float* Bptr0 = g_B[0] + (size_t)(j0 + lrow) * DDIM + tz * DQ + lc4;
    const float* Bptr1 = g_B[0] + (size_t)(j0 + 16 + lrow) * DDIM + tz * DQ + lc4;

    float* Ash = As[tz];
    float* Bsh = Bs[tz];

    float acc0[2][2] = {{0.f, 0.f}, {0.f, 0.f}};   // [ii][jj] class 0
    float acc1[2][2] = {{0.f, 0.f}, {0.f, 0.f}};   // [ii][jj] class 1

    // Prologue: prefetch chunk 0 (plain loads, no arithmetic in the shadow).
    float4 av  = *(const float4*)Aptr;
    float4 bv0 = *(const float4*)Bptr0;
    float4 bv1 = *(const float4*)Bptr1;

    for (int c = 0; c < DQ / 32; c++) {
        // Store current chunk (rows 8B-aligned -> float2 stores).
        *(float2*)&Ash[lrow * SPQ + lc4]            = make_float2(av.x, av.y);
        *(float2*)&Ash[lrow * SPQ + lc4 + 2]        = make_float2(av.z, av.w);
        *(float2*)&Bsh[lrow * SPQ + lc4]            = make_float2(bv0.x, bv0.y);
        *(float2*)&Bsh[lrow * SPQ + lc4 + 2]        = make_float2(bv0.z, bv0.w);
        *(float2*)&Bsh[(16 + lrow) * SPQ + lc4]     = make_float2(bv1.x, bv1.y);
        *(float2*)&Bsh[(16 + lrow) * SPQ + lc4 + 2] = make_float2(bv1.z, bv1.w);
        __syncthreads();

        // Prefetch next chunk: pure LDG, consumed only at next STS.
        if (c + 1 < DQ / 32) {
            const int off = (c + 1) * 32;
            av  = *(const float4*)(Aptr + off);
            bv0 = *(const float4*)(Bptr0 + off);
            bv1 = *(const float4*)(Bptr1 + off);
        }

        const float* Arow0 = &Ash[(2 * ty) * SPQ];
        const float* Arow1 = &Ash[(2 * ty + 1) * SPQ];
        const float* Brow0 = &Bsh[tx * SPQ];
        const float* Brow1 = &Bsh[(tx + 16) * SPQ];
        const float* W0h   = &W0a[tz * DQ + c * 32];
        const float* W1h   = &W1a[tz * DQ + c * 32];

#pragma unroll 8
        for (int dk = 0; dk < 32; dk += 2) {
            const float2 a0  = *(const float2*)&Arow0[dk];
            const float2 a1  = *(const float2*)&Arow1[dk];
            const float2 b0  = *(const float2*)&Brow0[dk];
            const float2 b1v = *(const float2*)&Brow1[dk];
            const float2 w0  = *(const float2*)&W0h[dk];
            const float2 w1  = *(const float2*)&W1h[dk];

            float th;
            // ii=0, jj=0
            asm("tanh.approx.f32 %0, %1;" : "=f"(th) : "f"(a0.x + b0.x));
            acc0[0][0] = fmaf(th, w0.x, acc0[0][0]);
            acc1[0][0] = fmaf(th, w1.x, acc1[0][0]);
            asm("tanh.approx.f32 %0, %1;" : "=f"(th) : "f"(a0.y + b0.y));
            acc0[0][0] = fmaf(th, w0.y, acc0[0][0]);
            acc1[0][0] = fmaf(th, w1.y, acc1[0][0]);
            // ii=0, jj=1
            asm("tanh.approx.f32 %0, %1;" : "=f"(th) : "f"(a0.x + b1v.x));
            acc0[0][1] = fmaf(th, w0.x, acc0[0][1]);
            acc1[0][1] = fmaf(th, w1.x, acc1[0][1]);
            asm("tanh.approx.f32 %0, %1;" : "=f"(th) : "f"(a0.y + b1v.y));
            acc0[0][1] = fmaf(th, w0.y, acc0[0][1]);
            acc1[0][1] = fmaf(th, w1.y, acc1[0][1]);
            // ii=1, jj=0
            asm("tanh.approx.f32 %0, %1;" : "=f"(th) : "f"(a1.x + b0.x));
            acc0[1][0] = fmaf(th, w0.x, acc0[1][0]);
            acc1[1][0] = fmaf(th, w1.x, acc1[1][0]);
            asm("tanh.approx.f32 %0, %1;" : "=f"(th) : "f"(a1.y + b0.y));
            acc0[1][0] = fmaf(th, w0.y, acc0[1][0]);
            acc1[1][0] = fmaf(th, w1.y, acc1[1][0]);
            // ii=1, jj=1
            asm("tanh.approx.f32 %0, %1;" : "=f"(th) : "f"(a1.x + b1v.x));
            acc0[1][1] = fmaf(th, w0.x, acc0[1][1]);
            acc1[1][1] = fmaf(th, w1.x, acc1[1][1]);
            asm("tanh.approx.f32 %0, %1;" : "=f"(th) : "f"(a1.y + b1v.y));
            acc0[1][1] = fmaf(th, w0.y, acc0[1][1]);
            acc1[1][1] = fmaf(th, w1.y, acc1[1][1]);
        }
        __syncthreads();
    }

    // Cross-quarter reduction: quarters 1..3 park 8 partials each, quarter 0 sums.
    if (tz > 0) {
        float* r = &Red[((tz - 1) * 128 + tt) * 8];
        *(float4*)r       = make_float4(acc0[0][0], acc0[0][1], acc0[1][0], acc0[1][1]);
        *(float4*)(r + 4) = make_float4(acc1[0][0], acc1[0][1], acc1[1][0], acc1[1][1]);
    }
    __syncthreads();
    if (tz == 0) {
#pragma unroll
        for (int q = 0; q < 3; q++) {
            const float* r = &Red[(q * 128 + tt) * 8];
            float4 p0 = *(const float4*)r;
            float4 p1 = *(const float4*)(r + 4);
            acc0[0][0] += p0.x; acc0[0][1] += p0.y; acc0[1][0] += p0.z; acc0[1][1] += p0.w;
            acc1[0][0] += p1.x; acc1[0][1] += p1.y; acc1[1][0] += p1.z; acc1[1][1] += p1.w;
        }
        const float bb0 = b2[0];
        const float bb1 = b2[1];
#pragma unroll
        for (int ii = 0; ii < 2; ii++) {
            const int i = i0 + 2 * ty + ii;
#pragma unroll
            for (int jj = 0; jj < 2; jj++) {
                const int j = j0 + tx + 16 * jj;
                float2 o = make_float2(acc0[ii][jj] + bb0, acc1[ii][jj] + bb1);
                *(float2*)(out + ((size_t)i * NROWS + j) * 2) = o;
            }
        }
    }
}

// ---------------------------------------------------------------------------
extern "C" void kernel_launch(void* const* d_in, const int* in_sizes, int n_in,
                              void* d_out, int out_size) {
    const float* P  = (const float*)d_in[0];   // [384, 768]
    const float* W1 = (const float*)d_in[1];   // [768, 1536]
    const float* b1 = (const float*)d_in[2];   // [768]
    const float* W2 = (const float*)d_in[3];   // [2, 768]
    const float* b2 = (const float*)d_in[4];   // [2]
    float* out = (float*)d_out;                // [384, 384, 2]

    gemm_kernel<<<dim3(24, 6, 2), 256>>>(P, W1, b1);
    fold_kernel<<<144, 256>>>();
    pair_kernel<<<dim3(12, 24), 512>>>(W2, b2, out);
}

// round 14
// speedup vs baseline: 1.9024x; 1.1108x over previous
#include <cuda_runtime.h>
#include <cuda_bf16.h>
#include <cstdint>

#define NROWS 384
#define DDIM  768
#define NCOLS 1536

// fp32 GEMM outputs (b1 folded into g_A).
__device__ float g_A[NROWS * DDIM];
__device__ float g_B[NROWS * DDIM];
// bf16 double-double operand buffers.
__device__ __nv_bfloat16 Xhi[NROWS * DDIM];
__device__ __nv_bfloat16 Xlo[NROWS * DDIM];
__device__ __nv_bfloat16 Whi[NCOLS * DDIM];   // Wt[n][k]; n in [0,1536)
__device__ __nv_bfloat16 Wlo[NCOLS * DDIM];

__device__ __forceinline__ uint32_t smem_u32(const void* p) {
    uint32_t a;
    asm("{ .reg .u64 t; cvta.to.shared.u64 t, %1; cvt.u32.u64 %0, t; }"
        : "=r"(a) : "l"(p));
    return a;
}
__device__ __forceinline__ void cp_async16(uint32_t dst, const void* src) {
    asm volatile("cp.async.ca.shared.global [%0], [%1], 16;"
                 :: "r"(dst), "l"(src) : "memory");
}
__device__ __forceinline__ void cp_commit() {
    asm volatile("cp.async.commit_group;" ::: "memory");
}
template <int N>
__device__ __forceinline__ void cp_wait() {
    asm volatile("cp.async.wait_group %0;" :: "n"(N) : "memory");
}
__device__ __forceinline__ void ldmatrix_x4(uint32_t& r0, uint32_t& r1,
                                            uint32_t& r2, uint32_t& r3,
                                            uint32_t addr) {
    asm volatile("ldmatrix.sync.aligned.m8n8.x4.shared.b16 {%0,%1,%2,%3}, [%4];"
                 : "=r"(r0), "=r"(r1), "=r"(r2), "=r"(r3) : "r"(addr));
}
__device__ __forceinline__ void mma_bf16(float* c, const uint32_t* a, const uint32_t* b) {
    asm volatile(
        "mma.sync.aligned.m16n8k16.row.col.f32.bf16.bf16.f32 "
        "{%0,%1,%2,%3}, {%4,%5,%6,%7}, {%8,%9}, {%0,%1,%2,%3};"
        : "+f"(c[0]), "+f"(c[1]), "+f"(c[2]), "+f"(c[3])
        : "r"(a[0]), "r"(a[1]), "r"(a[2]), "r"(a[3]), "r"(b[0]), "r"(b[1]));
}

// ===========================================================================
// Prep 1: split X = P into bf16 hi/lo. 294912 elems, 288x256, 4 per thread.
// ===========================================================================
__global__ void __launch_bounds__(256)
prep_x_kernel(const float* __restrict__ P) {
    const int i4 = (blockIdx.x * 256 + threadIdx.x) * 4;
    float4 v = *(const float4*)(P + i4);
    float x[4] = {v.x, v.y, v.z, v.w};
    __nv_bfloat16 h[4], l[4];
#pragma unroll
    for (int j = 0; j < 4; j++) {
        h[j] = __float2bfloat16(x[j]);
        l[j] = __float2bfloat16(x[j] - __bfloat162float(h[j]));
    }
    *(__nv_bfloat162*)(Xhi + i4)     = __halves2bfloat162(h[0], h[1]);
    *(__nv_bfloat162*)(Xhi + i4 + 2) = __halves2bfloat162(h[2], h[3]);
    *(__nv_bfloat162*)(Xlo + i4)     = __halves2bfloat162(l[0], l[1]);
    *(__nv_bfloat162*)(Xlo + i4 + 2) = __halves2bfloat162(l[2], l[3]);
}

// ===========================================================================
// Prep 2 (FIXED): W1 buffer is [768 out][1536 concat-k] (verified against the
// passing SIMT kernel's indexing). Wt[n][k] = W1[n mod 768][(n>=768)*768 + k]
// -- already k-contiguous, so this is a pure reindex + hi/lo split.
// 1536*768 elems, grid 1152 x 256, 4 per thread.
// ===========================================================================
__global__ void __launch_bounds__(256)
prep_w_kernel(const float* __restrict__ W1) {
    const int i4 = (blockIdx.x * 256 + threadIdx.x) * 4;  // flat into Wt[n][k]
    const int n  = i4 / DDIM;          // 0..1535
    const int k  = i4 - n * DDIM;      // multiple of 4
    const int srow = (n < DDIM) ? n : (n - DDIM);
    const int scol = (n < DDIM) ? k : (k + DDIM);
    float4 v = *(const float4*)(W1 + (size_t)srow * NCOLS + scol);
    float x[4] = {v.x, v.y, v.z, v.w};
    __nv_bfloat16 h[4], l[4];
#pragma unroll
    for (int j = 0; j < 4; j++) {
        h[j] = __float2bfloat16(x[j]);
        l[j] = __float2bfloat16(x[j] - __bfloat162float(h[j]));
    }
    *(__nv_bfloat162*)(Whi + i4)     = __halves2bfloat162(h[0], h[1]);
    *(__nv_bfloat162*)(Whi + i4 + 2) = __halves2bfloat162(h[2], h[3]);
    *(__nv_bfloat162*)(Wlo + i4)     = __halves2bfloat162(l[0], l[1]);
    *(__nv_bfloat162*)(Wlo + i4 + 2) = __halves2bfloat162(l[2], l[3]);
}

// ===========================================================================
// HMMA GEMM: C[m][n] = sum_k X[m,k] * Wt[n,k] via bf16 double-double
// (hi*hi + hi*lo + lo*hi), mma.sync m16n8k16 (baseline sm_80+ PTX).
// CTA 64(M) x 64(N), 4 warps (2m x 2n), each warp 32x32 = 2x4 m16n8 frags.
// k chunks of 32, cp.async double-buffered smem; Grid (24, 6) = 144 CTAs.
// Epilogue folds b1 and writes fp32 g_A / g_B.
// ===========================================================================
#define KC   32
#define SRS  40                    // smem row stride in bf16 (80 B)
#define NCH  (DDIM / KC)           // 24 chunks

__global__ void __launch_bounds__(128)
mma_gemm_kernel(const float* __restrict__ b1) {
    __shared__ __align__(16) __nv_bfloat16 Xs[2][2][64 * SRS];  // [buf][split]
    __shared__ __align__(16) __nv_bfloat16 Ws[2][2][64 * SRS];

    const int t    = threadIdx.x;      // 0..127
    const int lane = t & 31;
    const int wid  = t >> 5;           // 0..3
    const int wm   = wid >> 1;         // warp m 0..1
    const int wn   = wid & 1;          // warp n 0..1
    const int col0 = blockIdx.x * 64;  // global n base (0..1472)
    const int row0 = blockIdx.y * 64;  // global m base

    // cp.async mapping: 64 rows, 2 threads/row, each 2x16B per split.
    const int lrow = t >> 1;           // 0..63
    const int lofs = (t & 1) * 16;     // bf16 offset within 32-bf16 row

    const __nv_bfloat16* gx[2] = {
        Xhi + (size_t)(row0 + lrow) * DDIM + lofs,
        Xlo + (size_t)(row0 + lrow) * DDIM + lofs };
    const __nv_bfloat16* gw[2] = {
        Whi + (size_t)(col0 + lrow) * DDIM + lofs,
        Wlo + (size_t)(col0 + lrow) * DDIM + lofs };

    const uint32_t sXbase = smem_u32(&Xs[0][0][0]);
    const uint32_t sWbase = smem_u32(&Ws[0][0][0]);
    const uint32_t bufSz  = 2 * 64 * SRS * 2;   // bytes per buf (both splits)
    const uint32_t splSz  = 64 * SRS * 2;       // bytes per split

    // ldmatrix lane address components (canonical m16n8k16 mappings).
    const int a_r = (lane & 15);
    const int a_c = ((lane >> 4) << 3);
    const int b_r = ((lane >> 4) << 3) + (lane & 7);
    const int b_c = ((lane >> 3) & 1) * 8;

    float acc[2][4][4];
#pragma unroll
    for (int m = 0; m < 2; m++)
#pragma unroll
        for (int n = 0; n < 4; n++)
#pragma unroll
            for (int q = 0; q < 4; q++) acc[m][n][q] = 0.0f;

    auto load_chunk = [&](int buf, int c) {
        const int kc = c * KC;
#pragma unroll
        for (int s = 0; s < 2; s++) {
            uint32_t dx = sXbase + buf * bufSz + s * splSz + (lrow * SRS + lofs) * 2;
            cp_async16(dx,      gx[s] + kc);
            cp_async16(dx + 16, gx[s] + kc + 8);
            uint32_t dw = sWbase + buf * bufSz + s * splSz + (lrow * SRS + lofs) * 2;
            cp_async16(dw,      gw[s] + kc);
            cp_async16(dw + 16, gw[s] + kc + 8);
        }
    };

    load_chunk(0, 0);
    cp_commit();

    for (int c = 0; c < NCH; c++) {
        if (c + 1 < NCH) {
            load_chunk((c + 1) & 1, c + 1);
            cp_commit();
            cp_wait<1>();
        } else {
            cp_wait<0>();
        }
        __syncthreads();

        const int buf = c & 1;
        const uint32_t xb = sXbase + buf * bufSz;
        const uint32_t wb = sWbase + buf * bufSz;

#pragma unroll
        for (int kk = 0; kk < KC; kk += 16) {
            uint32_t ah[2][4], al[2][4];
#pragma unroll
            for (int mt = 0; mt < 2; mt++) {
                const int row = wm * 32 + mt * 16 + a_r;
                ldmatrix_x4(ah[mt][0], ah[mt][1], ah[mt][2], ah[mt][3],
                            xb + 0 * splSz + (row * SRS + kk + a_c) * 2);
                ldmatrix_x4(al[mt][0], al[mt][1], al[mt][2], al[mt][3],
                            xb + 1 * splSz + (row * SRS + kk + a_c) * 2);
            }
            uint32_t bh[4][2], bl[4][2];
#pragma unroll
            for (int np = 0; np < 2; np++) {
                const int nrow = wn * 32 + np * 16 + b_r;
                uint32_t r0, r1, r2, r3;
                ldmatrix_x4(r0, r1, r2, r3,
                            wb + 0 * splSz + (nrow * SRS + kk + b_c) * 2);
                bh[np * 2][0] = r0; bh[np * 2][1] = r1;
                bh[np * 2 + 1][0] = r2; bh[np * 2 + 1][1] = r3;
                ldmatrix_x4(r0, r1, r2, r3,
                            wb + 1 * splSz + (nrow * SRS + kk + b_c) * 2);
                bl[np * 2][0] = r0; bl[np * 2][1] = r1;
                bl[np * 2 + 1][0] = r2; bl[np * 2 + 1][1] = r3;
            }
#pragma unroll
            for (int m = 0; m < 2; m++)
#pragma unroll
                for (int n = 0; n < 4; n++) {
                    mma_bf16(acc[m][n], ah[m], bh[n]);   // hi*hi
                    mma_bf16(acc[m][n], ah[m], bl[n]);   // hi*lo
                    mma_bf16(acc[m][n], al[m], bh[n]);   // lo*hi
                }
        }
        __syncthreads();
    }

    // Epilogue: c0,c1 -> (row g, col 2tid..+1); c2,c3 -> row g+8.
    const int g   = lane >> 2;
    const int tid = lane & 3;
    const bool isA = (col0 < DDIM);
    float* dst = isA ? g_A : g_B;
    const int cb = isA ? 0 : DDIM;
#pragma unroll
    for (int mt = 0; mt < 2; mt++) {
        const int r0 = row0 + wm * 32 + mt * 16 + g;
#pragma unroll
        for (int nt = 0; nt < 4; nt++) {
            const int col = col0 + wn * 32 + nt * 8 + 2 * tid;
            float2 bv = make_float2(0.f, 0.f);
            if (isA) bv = *(const float2*)(b1 + col);
            *(float2*)(dst + (size_t)r0 * DDIM + col - cb) =
                make_float2(acc[mt][nt][0] + bv.x, acc[mt][nt][1] + bv.y);
            *(float2*)(dst + (size_t)(r0 + 8) * DDIM + col - cb) =
                make_float2(acc[mt][nt][2] + bv.x, acc[mt][nt][3] + bv.y);
        }
    }
}

// ===========================================================================
// Phase 2: fused  out[i,j,c] = sum_d tanh(A[i,d] + B[j,d]) * W2[c,d] + b2[c]
// (round-8 kernel verbatim; measured 29.4us.)
// ===========================================================================
#define SPQ 34
#define DQ  192

__global__ void __launch_bounds__(512, 2)
pair_kernel(const float* __restrict__ W2,
            const float* __restrict__ b2,
            float* __restrict__ out) {
    __shared__ float As[4][16 * SPQ];
    __shared__ float Bs[4][32 * SPQ];
    __shared__ float W0a[DDIM];
    __shared__ float W1a[DDIM];
    __shared__ float Red[3 * 128 * 8];

    const int t  = threadIdx.x;    // 0..511
    const int tz = t >> 7;         // d-quarter 0..3
    const int tt = t & 127;
    const int tx = tt & 15;
    const int ty = tt >> 4;
    const int i0 = blockIdx.y * 16;
    const int j0 = blockIdx.x * 32;

    if (t < 192) {
        *(float4*)&W0a[t << 2] = *(const float4*)(W2 + (t << 2));
    } else if (t < 384) {
        const int c4 = (t - 192) << 2;
        *(float4*)&W1a[c4] = *(const float4*)(W2 + DDIM + c4);
    }

    const int lrow = tt >> 3;           // 0..15
    const int lc4  = (tt & 7) << 2;     // 0..28
    const float* Aptr  = g_A + (size_t)(i0 + lrow) * DDIM + tz * DQ + lc4;
    const float* Bptr0 = g_B + (size_t)(j0 + lrow) * DDIM + tz * DQ + lc4;
    const float* Bptr1 = g_B + (size_t)(j0 + 16 + lrow) * DDIM + tz * DQ + lc4;

    float* Ash = As[tz];
    float* Bsh = Bs[tz];

    float acc0[2][2] = {{0.f, 0.f}, {0.f, 0.f}};
    float acc1[2][2] = {{0.f, 0.f}, {0.f, 0.f}};

    float4 av  = *(const float4*)Aptr;
    float4 bv0 = *(const float4*)Bptr0;
    float4 bv1 = *(const float4*)Bptr1;

    for (int c = 0; c < DQ / 32; c++) {
        *(float2*)&Ash[lrow * SPQ + lc4]            = make_float2(av.x, av.y);
        *(float2*)&Ash[lrow * SPQ + lc4 + 2]        = make_float2(av.z, av.w);
        *(float2*)&Bsh[lrow * SPQ + lc4]            = make_float2(bv0.x, bv0.y);
        *(float2*)&Bsh[lrow * SPQ + lc4 + 2]        = make_float2(bv0.z, bv0.w);
        *(float2*)&Bsh[(16 + lrow) * SPQ + lc4]     = make_float2(bv1.x, bv1.y);
        *(float2*)&Bsh[(16 + lrow) * SPQ + lc4 + 2] = make_float2(bv1.z, bv1.w);
        __syncthreads();

        if (c + 1 < DQ / 32) {
            const int off = (c + 1) * 32;
            av  = *(const float4*)(Aptr + off);
            bv0 = *(const float4*)(Bptr0 + off);
            bv1 = *(const float4*)(Bptr1 + off);
        }

        const float* Arow0 = &Ash[(2 * ty) * SPQ];
        const float* Arow1 = &Ash[(2 * ty + 1) * SPQ];
        const float* Brow0 = &Bsh[tx * SPQ];
        const float* Brow1 = &Bsh[(tx + 16) * SPQ];
        const float* W0h   = &W0a[tz * DQ + c * 32];
        const float* W1h   = &W1a[tz * DQ + c * 32];

#pragma unroll 8
        for (int dk = 0; dk < 32; dk += 2) {
            const float2 a0  = *(const float2*)&Arow0[dk];
            const float2 a1  = *(const float2*)&Arow1[dk];
            const float2 b0  = *(const float2*)&Brow0[dk];
            const float2 b1v = *(const float2*)&Brow1[dk];
            const float2 w0  = *(const float2*)&W0h[dk];
            const float2 w1  = *(const float2*)&W1h[dk];

            float th;
            asm("tanh.approx.f32 %0, %1;" : "=f"(th) : "f"(a0.x + b0.x));
            acc0[0][0] = fmaf(th, w0.x, acc0[0][0]);
            acc1[0][0] = fmaf(th, w1.x, acc1[0][0]);
            asm("tanh.approx.f32 %0, %1;" : "=f"(th) : "f"(a0.y + b0.y));
            acc0[0][0] = fmaf(th, w0.y, acc0[0][0]);
            acc1[0][0] = fmaf(th, w1.y, acc1[0][0]);
            asm("tanh.approx.f32 %0, %1;" : "=f"(th) : "f"(a0.x + b1v.x));
            acc0[0][1] = fmaf(th, w0.x, acc0[0][1]);
            acc1[0][1] = fmaf(th, w1.x, acc1[0][1]);
            asm("tanh.approx.f32 %0, %1;" : "=f"(th) : "f"(a0.y + b1v.y));
            acc0[0][1] = fmaf(th, w0.y, acc0[0][1]);
            acc1[0][1] = fmaf(th, w1.y, acc1[0][1]);
            asm("tanh.approx.f32 %0, %1;" : "=f"(th) : "f"(a1.x + b0.x));
            acc0[1][0] = fmaf(th, w0.x, acc0[1][0]);
            acc1[1][0] = fmaf(th, w1.x, acc1[1][0]);
            asm("tanh.approx.f32 %0, %1;" : "=f"(th) : "f"(a1.y + b0.y));
            acc0[1][0] = fmaf(th, w0.y, acc0[1][0]);
            acc1[1][0] = fmaf(th, w1.y, acc1[1][0]);
            asm("tanh.approx.f32 %0, %1;" : "=f"(th) : "f"(a1.x + b1v.x));
            acc0[1][1] = fmaf(th, w0.x, acc0[1][1]);
            acc1[1][1] = fmaf(th, w1.x, acc1[1][1]);
            asm("tanh.approx.f32 %0, %1;" : "=f"(th) : "f"(a1.y + b1v.y));
            acc0[1][1] = fmaf(th, w0.y, acc0[1][1]);
            acc1[1][1] = fmaf(th, w1.y, acc1[1][1]);
        }
        __syncthreads();
    }

    if (tz > 0) {
        float* r = &Red[((tz - 1) * 128 + tt) * 8];
        *(float4*)r       = make_float4(acc0[0][0], acc0[0][1], acc0[1][0], acc0[1][1]);
        *(float4*)(r + 4) = make_float4(acc1[0][0], acc1[0][1], acc1[1][0], acc1[1][1]);
    }
    __syncthreads();
    if (tz == 0) {
#pragma unroll
        for (int q = 0; q < 3; q++) {
            const float* r = &Red[(q * 128 + tt) * 8];
            float4 p0 = *(const float4*)r;
            float4 p1 = *(const float4*)(r + 4);
            acc0[0][0] += p0.x; acc0[0][1] += p0.y; acc0[1][0] += p0.z; acc0[1][1] += p0.w;
            acc1[0][0] += p1.x; acc1[0][1] += p1.y; acc1[1][0] += p1.z; acc1[1][1] += p1.w;
        }
        const float bb0 = b2[0];
        const float bb1 = b2[1];
#pragma unroll
        for (int ii = 0; ii < 2; ii++) {
            const int i = i0 + 2 * ty + ii;
#pragma unroll
            for (int jj = 0; jj < 2; jj++) {
                const int j = j0 + tx + 16 * jj;
                float2 o = make_float2(acc0[ii][jj] + bb0, acc1[ii][jj] + bb1);
                *(float2*)(out + ((size_t)i * NROWS + j) * 2) = o;
            }
        }
    }
}

// ---------------------------------------------------------------------------
extern "C" void kernel_launch(void* const* d_in, const int* in_sizes, int n_in,
                              void* d_out, int out_size) {
    const float* P  = (const float*)d_in[0];   // [384, 768]
    const float* W1 = (const float*)d_in[1];   // [768, 1536] (rows = out-neurons)
    const float* b1 = (const float*)d_in[2];   // [768]
    const float* W2 = (const float*)d_in[3];   // [2, 768]
    const float* b2 = (const float*)d_in[4];   // [2]
    float* out = (float*)d_out;                // [384, 384, 2]

    prep_x_kernel<<<288, 256>>>(P);
    prep_w_kernel<<<1152, 256>>>(W1);
    mma_gemm_kernel<<<dim3(24, 6), 128>>>(b1);
    pair_kernel<<<dim3(12, 24), 512>>>(W2, b2, out);
}